// round 16
// baseline (speedup 1.0000x reference)
#include <cuda_runtime.h>
#include <cuda_bf16.h>
#include <cstdint>

// Inputs (metadata order):
//   d_in[0] = z          float32 [12288, 128]
//   d_in[1] = edge_index int32 [2, 393216] (jnp.int64 silently downcast; detect)
//   d_in[2] = edge_attr  float32 [393216, 4]
//   d_in[3] = W          float32 [1, 256]
//   d_in[4] = b          float32 [1]
// Output: float32 [12288, 12288]
//
// out[r,c] = sum_dup(attr_sum) + (u[r]+v[c]+b) once per distinct cell.
// Structure (R15, best=117.4us):
//   mega:   [UV(48) | EDGE(1536) | ZERO(4736)], no spins. Prob term deferred
//           to scatter so EDGE never reads u/v.
//   scatter: sequential slot sweep; order-preserving hash => out stores
//           ascend in address. R16 change: __stwt on out stores — with
//           ascending addresses the write-through path can skip the 32B
//           write-allocate read per dirty line (halving scatter traffic)
//           without random-row activation cost.

#define N_NODES 12288
#define N_EDGES 393216

#define UV_BLOCKS    48     // 48*256 = 12288 threads, one per node
#define EDGE_BLOCKS  1536   // thread per edge
#define ZERO_BLOCKS  4736   // 148 SMs * 32

#define HASH_BITS 20
#define HASH_SIZE (1u << HASH_BITS)         // 1,048,576 slots (load ~0.37)
#define HASH_MASK (HASH_SIZE - 1u)
// floor(2^32 * HASH_SIZE / (N_NODES*N_NODES)) — monotonic multiply-shift
#define HASH_MULT 29826161ull

__device__ int   g_keys[HASH_SIZE];         // cell+1, 0 = empty; zero-init
__device__ float g_vals[HASH_SIZE];         // accumulated attr sums; zero-init
__device__ float g_u[N_NODES];              // dot(z[i], W[0:128]) + b
__device__ float g_v[N_NODES];              // dot(z[i], W[128:256])

// ---------------------------------------------------------------------------
__device__ __forceinline__ int block_detect_is64(const int* __restrict__ ei32,
                                                 int* sh_flag) {
    if (threadIdx.x < 32) {
        int w = ei32[2 * threadIdx.x + 1];
        unsigned any = __ballot_sync(0xFFFFFFFFu, w != 0);
        if (threadIdx.x == 0) *sh_flag = (any == 0u) ? 1 : 0;
    }
    __syncthreads();
    return *sh_flag;
}

__device__ __forceinline__ long long load_idx(const void* ei, size_t pos, int is64) {
    if (is64) return ((const long long*)ei)[pos];
    return (long long)((const int*)ei)[pos];
}

// order-preserving initial slot: cell scaled into [0, HASH_SIZE)
__device__ __forceinline__ unsigned hash_slot(unsigned cell) {
    return (unsigned)(((unsigned long long)cell * HASH_MULT) >> 32);
}

// ---------------------------------------------------------------------------
__global__ void mega_kernel(float4* __restrict__ out, size_t n4,
                            const void* __restrict__ ei,
                            const float4* __restrict__ attr,
                            const float* __restrict__ z,
                            const float* __restrict__ W,
                            const float* __restrict__ b) {
    __shared__ int sh_flag;
    int bid = blockIdx.x;

    if (bid < UV_BLOCKS) {
        // ---- u/v: thread-per-node dot, W staged in shared (2KB) ----
        __shared__ float4 sW1[32], sW2[32];
        if (threadIdx.x < 32) {
            sW1[threadIdx.x] = reinterpret_cast<const float4*>(W)[threadIdx.x];
            sW2[threadIdx.x] = reinterpret_cast<const float4*>(W + 128)[threadIdx.x];
        }
        __syncthreads();
        int node = bid * 256 + threadIdx.x;             // exactly covers 12288
        const float4* zrow = reinterpret_cast<const float4*>(z + (size_t)node * 128);
        float s1 = 0.f, s2 = 0.f;
        #pragma unroll
        for (int j = 0; j < 32; ++j) {
            float4 zv = zrow[j];
            float4 w1 = sW1[j], w2 = sW2[j];
            s1 += zv.x * w1.x + zv.y * w1.y + zv.z * w1.z + zv.w * w1.w;
            s2 += zv.x * w2.x + zv.y * w2.y + zv.z * w2.z + zv.w * w2.w;
        }
        g_u[node] = s1 + b[0];                          // bias folded into u
        g_v[node] = s2;
    } else if (bid < UV_BLOCKS + EDGE_BLOCKS) {
        // ---- edge phase: hash insert + attr-sum accumulate (no u/v) ----
        int is64 = block_detect_is64((const int*)ei, &sh_flag);
        int e = (bid - UV_BLOCKS) * 256 + threadIdx.x;
        if (e >= N_EDGES) return;
        long long r = load_idx(ei, e, is64);
        long long c = load_idx(ei, (size_t)N_EDGES + e, is64);
        if ((unsigned long long)r >= N_NODES || (unsigned long long)c >= N_NODES) return;

        float4 a = attr[e];
        unsigned cell = (unsigned)(r * N_NODES + c);
        int key = (int)cell + 1;                        // 0 reserved for empty
        float add = a.x + a.y + a.z + a.w;

        unsigned h = hash_slot(cell);
        while (true) {
            int prev = atomicCAS(&g_keys[h], 0, key);
            if (prev == 0 || prev == key) break;        // inserted or duplicate
            h = (h + 1u) & HASH_MASK;
        }
        atomicAdd(&g_vals[h], add);
    } else {
        // ---- zero the output: grid-stride float4 (validated floor) ----
        size_t i = (size_t)(bid - UV_BLOCKS - EDGE_BLOCKS) * blockDim.x + threadIdx.x;
        size_t stride = (size_t)ZERO_BLOCKS * blockDim.x;
        float4 zero = make_float4(0.f, 0.f, 0.f, 0.f);
        for (; i < n4; i += stride) out[i] = zero;
    }
}

// ---------------------------------------------------------------------------
// Scatter hash -> out. Ascending out stores (order-preserving hash); prob
// term added here once per distinct cell. __stwt: write-through, no
// L2 allocate — skips the per-line allocate-read, and these lines are never
// re-read. Slot restores stay normal (cached, reused next launch).
// ---------------------------------------------------------------------------
__global__ void scatter_kernel(float* __restrict__ out) {
    unsigned t = blockIdx.x * 256u + threadIdx.x;
    if (t >= HASH_SIZE) return;
    int k = g_keys[t];
    if (k > 0) {
        unsigned cell = (unsigned)(k - 1);
        unsigned r = cell / (unsigned)N_NODES;          // const-div -> mul
        unsigned c = cell - r * (unsigned)N_NODES;
        __stwt(&out[(size_t)cell], g_vals[t] + g_u[r] + g_v[c]);
        g_keys[t] = 0;
        g_vals[t] = 0.0f;
    }
}

// ---------------------------------------------------------------------------
extern "C" void kernel_launch(void* const* d_in, const int* in_sizes, int n_in,
                              void* d_out, int out_size) {
    const float*  z    = (const float*)d_in[0];
    const void*   ei   = d_in[1];
    const float4* attr = (const float4*)d_in[2];
    const float*  W    = (const float*)d_in[3];
    const float*  b    = (const float*)d_in[4];
    float*        out  = (float*)d_out;

    size_t n4 = (size_t)out_size / 4;

    mega_kernel<<<UV_BLOCKS + EDGE_BLOCKS + ZERO_BLOCKS, 256>>>(
        (float4*)out, n4, ei, attr, z, W, b);
    scatter_kernel<<<(HASH_SIZE + 255) / 256, 256>>>(out);
}